// round 15
// baseline (speedup 1.0000x reference)
#include <cuda_runtime.h>
#include <cuda_fp16.h>
#include <math.h>
#include <stdint.h>

#define BB 16
#define NN 784
#define CC 384
#define HH 8
#define HD 48
#define INNER 1152
#define MM (BB*NN)          // 12544
#define EPSV 1e-5f

// ---------------- scratch ----------------
__device__ __half g_xh[(size_t)MM * CC];
__device__ __half g_wqh[(size_t)INNER * CC];
__device__ __half g_wph[(size_t)CC * CC];
__device__ __half g_yh[(size_t)MM * INNER];     // qkv pre-norm, fp16 (28.9 MB)
__device__ __half g_ohsh[(size_t)MM * CC];      // hardswish(attn out), fp16
__device__ float  g_z[(size_t)MM * CC];         // proj pre-norm, fp32
__device__ __half g_bg[(size_t)HH * NN * NN + 64];   // pre-gathered bias*log2e, fp16
__device__ float  g_ps1[2*INNER];               // BN1 partial sums (sum | sumsq)
__device__ float  g_ps2[2*CC];                  // BN2 partial sums

// ---------------- helpers ----------------
__device__ __forceinline__ uint32_t pack2(float a, float b) {
    __half2 h = __floats2half2_rn(a, b);
    return *reinterpret_cast<uint32_t*>(&h);
}
__device__ __forceinline__ uint32_t smem_u32(const void* p) {
    return (uint32_t)__cvta_generic_to_shared(p);
}
__device__ __forceinline__ float ex2(float x) {        // MUFU.EX2
    float r;
    asm("ex2.approx.f32 %0, %1;" : "=f"(r) : "f"(x));
    return r;
}
__device__ __forceinline__ void mma_f16(float* c,
        uint32_t a0, uint32_t a1, uint32_t a2, uint32_t a3,
        uint32_t b0, uint32_t b1) {
    asm volatile("mma.sync.aligned.m16n8k16.row.col.f32.f16.f16.f32 "
                 "{%0,%1,%2,%3},{%4,%5,%6,%7},{%8,%9},{%0,%1,%2,%3};"
                 : "+f"(c[0]), "+f"(c[1]), "+f"(c[2]), "+f"(c[3])
                 : "r"(a0), "r"(a1), "r"(a2), "r"(a3), "r"(b0), "r"(b1));
}
__device__ __forceinline__ void ldsm4(uint32_t& r0, uint32_t& r1, uint32_t& r2, uint32_t& r3, uint32_t a) {
    asm volatile("ldmatrix.sync.aligned.m8n8.x4.shared.b16 {%0,%1,%2,%3}, [%4];"
                 : "=r"(r0),"=r"(r1),"=r"(r2),"=r"(r3) : "r"(a));
}
__device__ __forceinline__ void ldsm4t(uint32_t& r0, uint32_t& r1, uint32_t& r2, uint32_t& r3, uint32_t a) {
    asm volatile("ldmatrix.sync.aligned.m8n8.x4.trans.shared.b16 {%0,%1,%2,%3}, [%4];"
                 : "=r"(r0),"=r"(r1),"=r"(r2),"=r"(r3) : "r"(a));
}
__device__ __forceinline__ float hswish(float v) {
    return v * fminf(fmaxf(v + 3.f, 0.f), 6.f) * (1.0f/6.0f);
}

// ---------------- fp32->fp16 convert + zero BN partials ----------------
#define N4_X   (MM*CC/4)
#define N4_WQ  (INNER*CC/4)
#define N4_WP  (CC*CC/4)
#define N4_ALL (N4_X + N4_WQ + N4_WP)
__global__ __launch_bounds__(256) void f2h_all(const float* __restrict__ x,
                                               const float* __restrict__ wq,
                                               const float* __restrict__ wp) {
    int i = blockIdx.x * 256 + threadIdx.x;
    if (i >= N4_ALL) {
        int j = i - N4_ALL;
        if (j < 2*INNER) g_ps1[j] = 0.f;
        else if (j < 2*INNER + 2*CC) g_ps2[j - 2*INNER] = 0.f;
        return;
    }
    const float* in; __half* out; int idx;
    if (i < N4_X)              { in = x;  out = g_xh;  idx = i; }
    else if (i < N4_X + N4_WQ) { in = wq; out = g_wqh; idx = i - N4_X; }
    else                       { in = wp; out = g_wph; idx = i - N4_X - N4_WQ; }
    float4 v = ((const float4*)in)[idx];
    __half2* o = (__half2*)out;
    o[2*idx]   = __floats2half2_rn(v.x, v.y);
    o[2*idx+1] = __floats2half2_rn(v.z, v.w);
}

// ---------------- pre-gather bias ----------------
__global__ __launch_bounds__(256) void bias_expand(const float* __restrict__ biases) {
    int qi = blockIdx.x;
    int h  = blockIdx.y;
    __shared__ float br[NN];
    for (int i = threadIdx.x; i < NN; i += 256)
        br[i] = biases[h*NN + i] * 1.4426950408889634f;
    __syncthreads();
    int xi = qi / 28, yi = qi - xi*28;
    __half* dst = g_bg + ((size_t)h*NN + qi) * NN;
    for (int kj = threadIdx.x; kj < NN; kj += 256) {
        int xj = kj / 28, yj = kj - xj*28;
        dst[kj] = __float2half_rn(br[abs(xi-xj)*28 + abs(yi-yj)]);
    }
}

// ---------------- cp.async fp16 GEMM NT (K=384), 128x128 tile, 4-stage pipe ----------------
template<int OUTH>
__global__ __launch_bounds__(256) void gemm_cp(const __half* __restrict__ A,
                                               const __half* __restrict__ Bw,
                                               void* __restrict__ C, int Nn,
                                               float* __restrict__ ps) {
    extern __shared__ __half hs[];          // [4][2][128*40] = 81920 B
    const int STG = 128*40;
    int t = threadIdx.x;
    int w = t >> 5, L = t & 31;
    int g = L >> 2, c = L & 3;
    int wm = w & 3, wn = w >> 2;
    int m0 = blockIdx.y * 128, n0 = blockIdx.x * 128;

    int id0 = t, id1 = t + 256;
    int ra0 = id0 >> 2, oa0 = (id0 & 3) * 8;
    int ra1 = id1 >> 2, oa1 = (id1 & 3) * 8;
    const __half* Ap0 = A  + (size_t)(m0 + ra0) * 384 + oa0;
    const __half* Ap1 = A  + (size_t)(m0 + ra1) * 384 + oa1;
    const __half* Bp0 = Bw + (size_t)(n0 + ra0) * 384 + oa0;
    const __half* Bp1 = Bw + (size_t)(n0 + ra1) * 384 + oa1;

    uint32_t base = smem_u32(hs);
    uint32_t dA0 = base + (ra0*40 + oa0)*2;
    uint32_t dA1 = base + (ra1*40 + oa1)*2;
    uint32_t dB0 = base + (STG + ra0*40 + oa0)*2;
    uint32_t dB1 = base + (STG + ra1*40 + oa1)*2;

    int r8 = L & 7, sel = L >> 3;
    uint32_t aAddr = base + ((wm*32 + (L & 15))*40 + (L >> 4)*8)*2;
    uint32_t bAddr = base + STG*2 + ((wn*64 + (sel>>1)*8 + r8)*40 + (sel&1)*8)*2;

    #define ISSUE(st, kc) { \
        int ko = (kc) * 32; uint32_t so = (st) * (2*STG*2); \
        asm volatile("cp.async.ca.shared.global [%0], [%1], 16;" :: "r"(dA0+so), "l"(Ap0+ko)); \
        asm volatile("cp.async.ca.shared.global [%0], [%1], 16;" :: "r"(dA1+so), "l"(Ap1+ko)); \
        asm volatile("cp.async.ca.shared.global [%0], [%1], 16;" :: "r"(dB0+so), "l"(Bp0+ko)); \
        asm volatile("cp.async.ca.shared.global [%0], [%1], 16;" :: "r"(dB1+so), "l"(Bp1+ko)); \
        asm volatile("cp.async.commit_group;"); }

    float acc[2][8][4] = {};
    ISSUE(0, 0); ISSUE(1, 1); ISSUE(2, 2);

    for (int kc = 0; kc < 12; kc++) {
        if (kc < 10)       asm volatile("cp.async.wait_group 2;");
        else if (kc == 10) asm volatile("cp.async.wait_group 1;");
        else               asm volatile("cp.async.wait_group 0;");
        __syncthreads();
        if (kc + 3 < 12) { ISSUE((kc+3) & 3, kc+3); }
        uint32_t so = (kc & 3) * (2*STG*2);
        #pragma unroll
        for (int ks = 0; ks < 2; ks++) {
            uint32_t a0[2], a1[2], a2[2], a3[2];
            #pragma unroll
            for (int i = 0; i < 2; i++)
                ldsm4(a0[i], a1[i], a2[i], a3[i], aAddr + so + i*16*80 + ks*32);
            #pragma unroll
            for (int nbp = 0; nbp < 4; nbp++) {
                uint32_t b00, b10, b01, b11;
                ldsm4(b00, b10, b01, b11, bAddr + so + nbp*16*80 + ks*32);
                #pragma unroll
                for (int i = 0; i < 2; i++) {
                    mma_f16(acc[i][2*nbp],   a0[i], a1[i], a2[i], a3[i], b00, b10);
                    mma_f16(acc[i][2*nbp+1], a0[i], a1[i], a2[i], a3[i], b01, b11);
                }
            }
        }
    }
    #undef ISSUE

    // store + fused BN column stats on stored values
    float s0[8], s1[8], q0[8], q1[8];
    #pragma unroll
    for (int nb = 0; nb < 8; nb++) { s0[nb]=0.f; s1[nb]=0.f; q0[nb]=0.f; q1[nb]=0.f; }

    #pragma unroll
    for (int i = 0; i < 2; i++) {
        int row = m0 + wm*32 + i*16 + g;
        #pragma unroll
        for (int nb = 0; nb < 8; nb++) {
            int col = n0 + wn*64 + nb*8 + 2*c;
            float v0, v1, v2, v3;
            if (OUTH) {
                __half2 h0 = __floats2half2_rn(acc[i][nb][0], acc[i][nb][1]);
                __half2 h1 = __floats2half2_rn(acc[i][nb][2], acc[i][nb][3]);
                __half2* Ch = (__half2*)C;
                Ch[((size_t)row*Nn + col) >> 1]     = h0;
                Ch[((size_t)(row+8)*Nn + col) >> 1] = h1;
                float2 f0 = __half22float2(h0), f1 = __half22float2(h1);
                v0=f0.x; v1=f0.y; v2=f1.x; v3=f1.y;
            } else {
                float* Cf = (float*)C;
                *(float2*)(Cf + (size_t)row*Nn + col)     = make_float2(acc[i][nb][0], acc[i][nb][1]);
                *(float2*)(Cf + (size_t)(row+8)*Nn + col) = make_float2(acc[i][nb][2], acc[i][nb][3]);
                v0=acc[i][nb][0]; v1=acc[i][nb][1]; v2=acc[i][nb][2]; v3=acc[i][nb][3];
            }
            s0[nb] += v0 + v2;  q0[nb] += v0*v0 + v2*v2;
            s1[nb] += v1 + v3;  q1[nb] += v1*v1 + v3*v3;
        }
    }
    #pragma unroll
    for (int nb = 0; nb < 8; nb++) {
        #pragma unroll
        for (int m = 4; m <= 16; m <<= 1) {
            s0[nb] += __shfl_xor_sync(0xffffffffu, s0[nb], m);
            s1[nb] += __shfl_xor_sync(0xffffffffu, s1[nb], m);
            q0[nb] += __shfl_xor_sync(0xffffffffu, q0[nb], m);
            q1[nb] += __shfl_xor_sync(0xffffffffu, q1[nb], m);
        }
    }
    float* cs_  = (float*)hs;          // [128]
    float* cs2_ = (float*)hs + 128;    // [128]
    __syncthreads();
    if (t < 128) { cs_[t] = 0.f; cs2_[t] = 0.f; }
    __syncthreads();
    if (g == 0) {
        #pragma unroll
        for (int nb = 0; nb < 8; nb++) {
            int lc0 = wn*64 + nb*8 + 2*c;
            atomicAdd(&cs_[lc0],      s0[nb]);
            atomicAdd(&cs_[lc0 + 1],  s1[nb]);
            atomicAdd(&cs2_[lc0],     q0[nb]);
            atomicAdd(&cs2_[lc0 + 1], q1[nb]);
        }
    }
    __syncthreads();
    if (t < 128) {
        int gcol = n0 + t;
        atomicAdd(&ps[gcol],      cs_[t]);
        atomicAdd(&ps[Nn + gcol], cs2_[t]);
    }
}

// ---------------- fused attention: 4-stage K/V pipe, direct-LDG bias, peeled tail ----------------
// smem halfs: Qh @0 [112][56] (6272), Kh @6272 4x[64][56] (14336), Vh @20608 4x[64][56] (14336)
// floats from word 17472: uRow[112], consts 6x[48]
// total = 71488 bytes
__global__ __launch_bounds__(224, 2) void attn_kernel(const __half* __restrict__ Y,
                                                      const __half* __restrict__ Bg,
                                                      const float* __restrict__ ps1,
                                                      const float* __restrict__ g1,
                                                      const float* __restrict__ b1,
                                                      __half* __restrict__ Ohs) {
    extern __shared__ uint32_t sm[];
    float* smf = (float*)sm;
    const int QH = 0, KH = 6272, VH = 20608;
    const int STAGE = 64*56;
    float* uRow = smf + 17472;
    float* aq = smf + 17584; float* bq = smf + 17632;
    float* ak = smf + 17680; float* bk = smf + 17728;
    float* cv = smf + 17776; float* ev = smf + 17824;

    int t = threadIdx.x;
    int w = t >> 5, L = t & 31;
    int g = L >> 2, c = L & 3;
    int m0l = w * 16;
    int bh = blockIdx.y;
    int b = bh >> 3, h = bh & 7;
    int q0 = blockIdx.x * 112;

    uint32_t base = smem_u32(sm);
    uint32_t kBase = base + KH*2, vBase = base + VH*2;

    #define ISSUE_TILE(kt, stage) { \
        int k0i = (kt) * 64; \
        _Pragma("unroll") \
        for (int j = 0; j < 4; j++) { \
            int idx = t + 224*j; \
            if (j < 3 || idx < 768) { \
                int hv  = idx >= 384; \
                int rem = idx - hv*384; \
                int row = rem / 6, seg = rem - row*6; \
                int n = k0i + row; if (n > NN-1) n = NN-1; \
                const __half* src = Y + (size_t)(b*NN + n)*INNER + (hv ? 768 : 384) + h*HD + seg*8; \
                uint32_t dst = (hv ? vBase : kBase) + (stage)*STAGE*2 + (row*56 + seg*8)*2; \
                asm volatile("cp.async.ca.shared.global [%0], [%1], 16;" :: "r"(dst), "l"(src)); \
            } \
        } \
        asm volatile("cp.async.commit_group;"); }

    ISSUE_TILE(0, 0);
    ISSUE_TILE(1, 1);
    ISSUE_TILE(2, 2);

    // fold constants from BN1 partial sums
    for (int i = t; i < 288; i += 224) {
        int which = i / 48, d = i - which*48;
        int p = which >> 1;
        int ch = p*CC + h*HD + d;
        float mean = ps1[ch] * (1.0f/MM);
        float var  = ps1[INNER + ch] * (1.0f/MM) - mean*mean;
        float sc   = g1[ch] * rsqrtf(var + EPSV);
        float v = (which & 1) ? (b1[ch] - mean*sc) : sc;
        smf[17584 + which*48 + d] = v;
    }
    __syncthreads();

    const float scale = 0.14433756729740643f;
    const float cs = scale * 1.4426950408889634f;

    // Q load + BN fold
    {
        int row = t >> 1, ds = (t & 1) * 24;
        const __half2* src = (const __half2*)(Y + (size_t)(b*NN + q0 + row)*INNER + h*HD + ds);
        float tpart = 0.f;
        #pragma unroll
        for (int j = 0; j < 12; j++) {
            int d = ds + 2*j;
            float2 f = __half22float2(src[j]);
            float q0f = fmaf(f.x, aq[d],   bq[d]);
            float q1f = fmaf(f.y, aq[d+1], bq[d+1]);
            tpart = fmaf(q0f, bk[d], tpart);
            tpart = fmaf(q1f, bk[d+1], tpart);
            sm[QH/2 + row*28 + ds/2 + j] = pack2(q0f*ak[d], q1f*ak[d+1]);
        }
        tpart += __shfl_xor_sync(0xffffffffu, tpart, 1);
        if ((t & 1) == 0) uRow[row] = cs * tpart;
    }
    __syncthreads();

    uint32_t qA = base + QH*2 + ((m0l + (L & 15))*56 + (L >> 4)*8)*2;
    uint32_t qa0[3], qa1[3], qa2[3], qa3[3];
    #pragma unroll
    for (int ks = 0; ks < 3; ks++)
        ldsm4(qa0[ks], qa1[ks], qa2[ks], qa3[ks], qA + ks*32);
    float u0 = uRow[m0l + g];
    float u1 = uRow[m0l + 8 + g];

    int r8 = L & 7, sel = L >> 3;
    uint32_t kB_rel = (uint32_t)((((sel >> 1)*8 + r8)*56 + (sel & 1)*8)*2);
    uint32_t vB_rel = (uint32_t)((((sel & 1)*8 + r8)*56)*2 + (sel >> 1)*16);

    int qr0 = q0 + m0l + g;
    const __half2* bp0 = (const __half2*)(Bg + ((size_t)h*NN + qr0) * NN);
    const __half2* bp1 = (const __half2*)(Bg + ((size_t)h*NN + qr0 + 8) * NN);

    float Oc[6][4] = {};
    float lsum0 = 0.f, lsum1 = 0.f;

    #define DO_TILE(kt, CHECKED) { \
        int k0 = (kt) * 64; \
        uint32_t so = ((kt) & 3) * STAGE*2; \
        if ((kt) < 10)       asm volatile("cp.async.wait_group 2;"); \
        else if ((kt) == 10) asm volatile("cp.async.wait_group 1;"); \
        else                 asm volatile("cp.async.wait_group 0;"); \
        __syncthreads(); \
        if ((kt) + 3 < 13) { ISSUE_TILE((kt) + 3, ((kt) + 3) & 3); } \
        float Sc[8][4] = {}; \
        _Pragma("unroll") \
        for (int ks = 0; ks < 3; ks++) { \
            _Pragma("unroll") \
            for (int nbp = 0; nbp < 4; nbp++) { \
                uint32_t b00, b10, b01, b11; \
                ldsm4(b00, b10, b01, b11, kBase + so + nbp*16*112 + ks*32 + kB_rel); \
                mma_f16(Sc[2*nbp],   qa0[ks], qa1[ks], qa2[ks], qa3[ks], b00, b10); \
                mma_f16(Sc[2*nbp+1], qa0[ks], qa1[ks], qa2[ks], qa3[ks], b01, b11); \
            } \
        } \
        float Pv[8][4]; \
        _Pragma("unroll") \
        for (int nb = 0; nb < 8; nb++) { \
            int kj = k0 + nb*8 + 2*c; \
            float p0 = 0.f, p1 = 0.f, p2 = 0.f, p3 = 0.f; \
            if (!CHECKED || kj < NN) { \
                float2 bf0 = __half22float2(bp0[kj >> 1]); \
                float2 bf1 = __half22float2(bp1[kj >> 1]); \
                p0 = ex2(fmaf(Sc[nb][0], cs, u0 + bf0.x)); \
                p2 = ex2(fmaf(Sc[nb][2], cs, u1 + bf1.x)); \
                if (!CHECKED || kj + 1 < NN) { \
                    p1 = ex2(fmaf(Sc[nb][1], cs, u0 + bf0.y)); \
                    p3 = ex2(fmaf(Sc[nb][3], cs, u1 + bf1.y)); \
                } \
            } \
            Pv[nb][0] = p0; Pv[nb][1] = p1; Pv[nb][2] = p2; Pv[nb][3] = p3; \
            lsum0 += p0 + p1; lsum1 += p2 + p3; \
        } \
        _Pragma("unroll") \
        for (int ks = 0; ks < 4; ks++) { \
            uint32_t a0 = pack2(Pv[2*ks][0],   Pv[2*ks][1]); \
            uint32_t a1 = pack2(Pv[2*ks][2],   Pv[2*ks][3]); \
            uint32_t a2 = pack2(Pv[2*ks+1][0], Pv[2*ks+1][1]); \
            uint32_t a3 = pack2(Pv[2*ks+1][2], Pv[2*ks+1][3]); \
            _Pragma("unroll") \
            for (int nbp = 0; nbp < 3; nbp++) { \
                uint32_t b00, b10, b01, b11; \
                ldsm4t(b00, b10, b01, b11, vBase + so + ks*16*112 + nbp*32 + vB_rel); \
                mma_f16(Oc[2*nbp],   a0, a1, a2, a3, b00, b10); \
                mma_f16(Oc[2*nbp+1], a0, a1, a2, a3, b01, b11); \
            } \
        } }

    for (int kt = 0; kt < 12; kt++) DO_TILE(kt, 0);
    DO_TILE(12, 1);
    #undef DO_TILE
    #undef ISSUE_TILE

    lsum0 += __shfl_xor_sync(0xffffffffu, lsum0, 1);
    lsum0 += __shfl_xor_sync(0xffffffffu, lsum0, 2);
    lsum1 += __shfl_xor_sync(0xffffffffu, lsum1, 1);
    lsum1 += __shfl_xor_sync(0xffffffffu, lsum1, 2);

    float inv0 = 1.0f / lsum0;
    float inv1 = 1.0f / lsum1;
    int n0g = q0 + m0l + g, n1g = n0g + 8;
    __half2* O2 = (__half2*)Ohs;
    #pragma unroll
    for (int nb = 0; nb < 6; nb++) {
        int d = nb*8 + 2*c;
        float o00 = fmaf(Oc[nb][0]*inv0, cv[d],   ev[d]);
        float o01 = fmaf(Oc[nb][1]*inv0, cv[d+1], ev[d+1]);
        float o10 = fmaf(Oc[nb][2]*inv1, cv[d],   ev[d]);
        float o11 = fmaf(Oc[nb][3]*inv1, cv[d+1], ev[d+1]);
        O2[((size_t)(b*NN + n0g)*CC + h*HD + d) >> 1] = __floats2half2_rn(hswish(o00), hswish(o01));
        O2[((size_t)(b*NN + n1g)*CC + h*HD + d) >> 1] = __floats2half2_rn(hswish(o10), hswish(o11));
    }
}

// ---------------- final BN apply (stats from ps2) ----------------
__global__ __launch_bounds__(256) void apply_bn(const float* __restrict__ Z,
                                                const float* __restrict__ ps2,
                                                const float* __restrict__ gamma,
                                                const float* __restrict__ beta,
                                                float* __restrict__ out) {
    size_t base = ((size_t)blockIdx.x * 256 + threadIdx.x) * 4;
    if (base < (size_t)MM * CC) {
        float4 z = *(const float4*)(Z + base);
        int c = (int)(base % CC);
        float o[4];
        float zv[4] = {z.x, z.y, z.z, z.w};
        #pragma unroll
        for (int j = 0; j < 4; j++) {
            int cc = c + j;
            float mean = ps2[cc] * (1.0f/MM);
            float var  = ps2[CC + cc] * (1.0f/MM) - mean*mean;
            float sc   = gamma[cc] * rsqrtf(var + EPSV);
            o[j] = zv[j] * sc + (beta[cc] - mean * sc);
        }
        *(float4*)(out + base) = make_float4(o[0], o[1], o[2], o[3]);
    }
}

extern "C" void kernel_launch(void* const* d_in, const int* in_sizes, int n_in,
                              void* d_out, int out_size) {
    const float* x      = (const float*)d_in[0];
    const float* Wqkv   = (const float*)d_in[1];
    const float* g1     = (const float*)d_in[2];
    const float* b1     = (const float*)d_in[3];
    const float* Wproj  = (const float*)d_in[4];
    const float* g2     = (const float*)d_in[5];
    const float* b2     = (const float*)d_in[6];
    const float* biases = (const float*)d_in[7];
    float* out = (float*)d_out;

    __half *xh, *wqh, *wph, *yh, *ohsh, *bg;
    float *zp, *ps1, *ps2;
    cudaGetSymbolAddress((void**)&xh,   g_xh);
    cudaGetSymbolAddress((void**)&wqh,  g_wqh);
    cudaGetSymbolAddress((void**)&wph,  g_wph);
    cudaGetSymbolAddress((void**)&yh,   g_yh);
    cudaGetSymbolAddress((void**)&ohsh, g_ohsh);
    cudaGetSymbolAddress((void**)&zp,   g_z);
    cudaGetSymbolAddress((void**)&bg,   g_bg);
    cudaGetSymbolAddress((void**)&ps1,  g_ps1);
    cudaGetSymbolAddress((void**)&ps2,  g_ps2);

    cudaFuncSetAttribute(gemm_cp<1>, cudaFuncAttributeMaxDynamicSharedMemorySize, 81920);
    cudaFuncSetAttribute(gemm_cp<0>, cudaFuncAttributeMaxDynamicSharedMemorySize, 81920);
    cudaFuncSetAttribute(attn_kernel, cudaFuncAttributeMaxDynamicSharedMemorySize, 71488);

    int nthreads = N4_ALL + 2*INNER + 2*CC;
    f2h_all<<<(nthreads + 255)/256, 256>>>(x, Wqkv, Wproj);
    bias_expand<<<dim3(NN, HH), 256>>>(biases);

    gemm_cp<1><<<dim3(INNER/128, MM/128), 256, 81920>>>(xh, wqh, yh, INNER, ps1);
    attn_kernel<<<dim3(7, BB*HH), 224, 71488>>>(yh, bg, ps1, g1, b1, ohsh);
    gemm_cp<0><<<dim3(CC/128, MM/128), 256, 81920>>>(ohsh, wph, zp, CC, ps2);
    apply_bn<<<(MM*CC/4 + 255)/256, 256>>>(zp, ps2, g2, b2, out);
}

// round 16
// speedup vs baseline: 1.0230x; 1.0230x over previous
#include <cuda_runtime.h>
#include <cuda_fp16.h>
#include <math.h>
#include <stdint.h>

#define BB 16
#define NN 784
#define CC 384
#define HH 8
#define HD 48
#define INNER 1152
#define MM (BB*NN)          // 12544
#define EPSV 1e-5f
#define BGW 832             // padded, permuted bias row width (13*64)

// ---------------- scratch ----------------
__device__ __half g_xh[(size_t)MM * CC];
__device__ __half g_wqh[(size_t)INNER * CC];
__device__ __half g_wph[(size_t)CC * CC];
__device__ __half g_yh[(size_t)MM * INNER];     // qkv pre-norm, fp16 (28.9 MB)
__device__ __half g_ohsh[(size_t)MM * CC];      // hardswish(attn out), fp16
__device__ float  g_z[(size_t)MM * CC];         // proj pre-norm, fp32
__device__ __half g_bg[(size_t)HH * NN * BGW + 64];  // permuted pre-gathered bias*log2e
__device__ float  g_ps1[2*INNER];               // BN1 partial sums (sum | sumsq)
__device__ float  g_ps2[2*CC];                  // BN2 partial sums

// ---------------- helpers ----------------
__device__ __forceinline__ uint32_t pack2(float a, float b) {
    __half2 h = __floats2half2_rn(a, b);
    return *reinterpret_cast<uint32_t*>(&h);
}
__device__ __forceinline__ uint32_t smem_u32(const void* p) {
    return (uint32_t)__cvta_generic_to_shared(p);
}
__device__ __forceinline__ float ex2(float x) {        // MUFU.EX2
    float r;
    asm("ex2.approx.f32 %0, %1;" : "=f"(r) : "f"(x));
    return r;
}
__device__ __forceinline__ void mma_f16(float* c,
        uint32_t a0, uint32_t a1, uint32_t a2, uint32_t a3,
        uint32_t b0, uint32_t b1) {
    asm volatile("mma.sync.aligned.m16n8k16.row.col.f32.f16.f16.f32 "
                 "{%0,%1,%2,%3},{%4,%5,%6,%7},{%8,%9},{%0,%1,%2,%3};"
                 : "+f"(c[0]), "+f"(c[1]), "+f"(c[2]), "+f"(c[3])
                 : "r"(a0), "r"(a1), "r"(a2), "r"(a3), "r"(b0), "r"(b1));
}
__device__ __forceinline__ void ldsm4(uint32_t& r0, uint32_t& r1, uint32_t& r2, uint32_t& r3, uint32_t a) {
    asm volatile("ldmatrix.sync.aligned.m8n8.x4.shared.b16 {%0,%1,%2,%3}, [%4];"
                 : "=r"(r0),"=r"(r1),"=r"(r2),"=r"(r3) : "r"(a));
}
__device__ __forceinline__ void ldsm4t(uint32_t& r0, uint32_t& r1, uint32_t& r2, uint32_t& r3, uint32_t a) {
    asm volatile("ldmatrix.sync.aligned.m8n8.x4.trans.shared.b16 {%0,%1,%2,%3}, [%4];"
                 : "=r"(r0),"=r"(r1),"=r"(r2),"=r"(r3) : "r"(a));
}
__device__ __forceinline__ float hswish(float v) {
    return v * fminf(fmaxf(v + 3.f, 0.f), 6.f) * (1.0f/6.0f);
}

// ---------------- fp32->fp16 convert + zero BN partials ----------------
#define N4_X   (MM*CC/4)
#define N4_WQ  (INNER*CC/4)
#define N4_WP  (CC*CC/4)
#define N4_ALL (N4_X + N4_WQ + N4_WP)
__global__ __launch_bounds__(256) void f2h_all(const float* __restrict__ x,
                                               const float* __restrict__ wq,
                                               const float* __restrict__ wp) {
    int i = blockIdx.x * 256 + threadIdx.x;
    if (i >= N4_ALL) {
        int j = i - N4_ALL;
        if (j < 2*INNER) g_ps1[j] = 0.f;
        else if (j < 2*INNER + 2*CC) g_ps2[j - 2*INNER] = 0.f;
        return;
    }
    const float* in; __half* out; int idx;
    if (i < N4_X)              { in = x;  out = g_xh;  idx = i; }
    else if (i < N4_X + N4_WQ) { in = wq; out = g_wqh; idx = i - N4_X; }
    else                       { in = wp; out = g_wph; idx = i - N4_X - N4_WQ; }
    float4 v = ((const float4*)in)[idx];
    __half2* o = (__half2*)out;
    o[2*idx]   = __floats2half2_rn(v.x, v.y);
    o[2*idx+1] = __floats2half2_rn(v.z, v.w);
}

// ---------------- pre-gather bias (permuted: within 64-block, s = d*8 + nb) ----------------
__global__ __launch_bounds__(256) void bias_expand(const float* __restrict__ biases) {
    int qi = blockIdx.x;
    int h  = blockIdx.y;
    __shared__ float br[NN];
    for (int i = threadIdx.x; i < NN; i += 256)
        br[i] = biases[h*NN + i] * 1.4426950408889634f;
    __syncthreads();
    int xi = qi / 28, yi = qi - xi*28;
    __half* dst = g_bg + ((size_t)h*NN + qi) * BGW;
    for (int s = threadIdx.x; s < BGW; s += 256) {
        int blk = s >> 6, s6 = s & 63;
        int l = (s6 & 7) * 8 + (s6 >> 3);      // inverse permutation
        int kj = blk * 64 + l;
        float v = 0.f;
        if (kj < NN) {
            int xj = kj / 28, yj = kj - xj*28;
            v = br[abs(xi-xj)*28 + abs(yi-yj)];
        }
        dst[s] = __float2half_rn(v);
    }
}

// ---------------- cp.async fp16 GEMM NT (K=384), 128x128 tile, 4-stage pipe ----------------
template<int OUTH>
__global__ __launch_bounds__(256) void gemm_cp(const __half* __restrict__ A,
                                               const __half* __restrict__ Bw,
                                               void* __restrict__ C, int Nn,
                                               float* __restrict__ ps) {
    extern __shared__ __half hs[];          // [4][2][128*40] = 81920 B
    const int STG = 128*40;
    int t = threadIdx.x;
    int w = t >> 5, L = t & 31;
    int g = L >> 2, c = L & 3;
    int wm = w & 3, wn = w >> 2;
    int m0 = blockIdx.y * 128, n0 = blockIdx.x * 128;

    int id0 = t, id1 = t + 256;
    int ra0 = id0 >> 2, oa0 = (id0 & 3) * 8;
    int ra1 = id1 >> 2, oa1 = (id1 & 3) * 8;
    const __half* Ap0 = A  + (size_t)(m0 + ra0) * 384 + oa0;
    const __half* Ap1 = A  + (size_t)(m0 + ra1) * 384 + oa1;
    const __half* Bp0 = Bw + (size_t)(n0 + ra0) * 384 + oa0;
    const __half* Bp1 = Bw + (size_t)(n0 + ra1) * 384 + oa1;

    uint32_t base = smem_u32(hs);
    uint32_t dA0 = base + (ra0*40 + oa0)*2;
    uint32_t dA1 = base + (ra1*40 + oa1)*2;
    uint32_t dB0 = base + (STG + ra0*40 + oa0)*2;
    uint32_t dB1 = base + (STG + ra1*40 + oa1)*2;

    int r8 = L & 7, sel = L >> 3;
    uint32_t aAddr = base + ((wm*32 + (L & 15))*40 + (L >> 4)*8)*2;
    uint32_t bAddr = base + STG*2 + ((wn*64 + (sel>>1)*8 + r8)*40 + (sel&1)*8)*2;

    #define ISSUE(st, kc) { \
        int ko = (kc) * 32; uint32_t so = (st) * (2*STG*2); \
        asm volatile("cp.async.ca.shared.global [%0], [%1], 16;" :: "r"(dA0+so), "l"(Ap0+ko)); \
        asm volatile("cp.async.ca.shared.global [%0], [%1], 16;" :: "r"(dA1+so), "l"(Ap1+ko)); \
        asm volatile("cp.async.ca.shared.global [%0], [%1], 16;" :: "r"(dB0+so), "l"(Bp0+ko)); \
        asm volatile("cp.async.ca.shared.global [%0], [%1], 16;" :: "r"(dB1+so), "l"(Bp1+ko)); \
        asm volatile("cp.async.commit_group;"); }

    float acc[2][8][4] = {};
    ISSUE(0, 0); ISSUE(1, 1); ISSUE(2, 2);

    for (int kc = 0; kc < 12; kc++) {
        if (kc < 10)       asm volatile("cp.async.wait_group 2;");
        else if (kc == 10) asm volatile("cp.async.wait_group 1;");
        else               asm volatile("cp.async.wait_group 0;");
        __syncthreads();
        if (kc + 3 < 12) { ISSUE((kc+3) & 3, kc+3); }
        uint32_t so = (kc & 3) * (2*STG*2);
        #pragma unroll
        for (int ks = 0; ks < 2; ks++) {
            uint32_t a0[2], a1[2], a2[2], a3[2];
            #pragma unroll
            for (int i = 0; i < 2; i++)
                ldsm4(a0[i], a1[i], a2[i], a3[i], aAddr + so + i*16*80 + ks*32);
            #pragma unroll
            for (int nbp = 0; nbp < 4; nbp++) {
                uint32_t b00, b10, b01, b11;
                ldsm4(b00, b10, b01, b11, bAddr + so + nbp*16*80 + ks*32);
                #pragma unroll
                for (int i = 0; i < 2; i++) {
                    mma_f16(acc[i][2*nbp],   a0[i], a1[i], a2[i], a3[i], b00, b10);
                    mma_f16(acc[i][2*nbp+1], a0[i], a1[i], a2[i], a3[i], b01, b11);
                }
            }
        }
    }
    #undef ISSUE

    // store + fused BN column stats on stored values
    float s0[8], s1[8], q0[8], q1[8];
    #pragma unroll
    for (int nb = 0; nb < 8; nb++) { s0[nb]=0.f; s1[nb]=0.f; q0[nb]=0.f; q1[nb]=0.f; }

    #pragma unroll
    for (int i = 0; i < 2; i++) {
        int row = m0 + wm*32 + i*16 + g;
        #pragma unroll
        for (int nb = 0; nb < 8; nb++) {
            int col = n0 + wn*64 + nb*8 + 2*c;
            float v0, v1, v2, v3;
            if (OUTH) {
                __half2 h0 = __floats2half2_rn(acc[i][nb][0], acc[i][nb][1]);
                __half2 h1 = __floats2half2_rn(acc[i][nb][2], acc[i][nb][3]);
                __half2* Ch = (__half2*)C;
                Ch[((size_t)row*Nn + col) >> 1]     = h0;
                Ch[((size_t)(row+8)*Nn + col) >> 1] = h1;
                float2 f0 = __half22float2(h0), f1 = __half22float2(h1);
                v0=f0.x; v1=f0.y; v2=f1.x; v3=f1.y;
            } else {
                float* Cf = (float*)C;
                *(float2*)(Cf + (size_t)row*Nn + col)     = make_float2(acc[i][nb][0], acc[i][nb][1]);
                *(float2*)(Cf + (size_t)(row+8)*Nn + col) = make_float2(acc[i][nb][2], acc[i][nb][3]);
                v0=acc[i][nb][0]; v1=acc[i][nb][1]; v2=acc[i][nb][2]; v3=acc[i][nb][3];
            }
            s0[nb] += v0 + v2;  q0[nb] += v0*v0 + v2*v2;
            s1[nb] += v1 + v3;  q1[nb] += v1*v1 + v3*v3;
        }
    }
    #pragma unroll
    for (int nb = 0; nb < 8; nb++) {
        #pragma unroll
        for (int m = 4; m <= 16; m <<= 1) {
            s0[nb] += __shfl_xor_sync(0xffffffffu, s0[nb], m);
            s1[nb] += __shfl_xor_sync(0xffffffffu, s1[nb], m);
            q0[nb] += __shfl_xor_sync(0xffffffffu, q0[nb], m);
            q1[nb] += __shfl_xor_sync(0xffffffffu, q1[nb], m);
        }
    }
    float* cs_  = (float*)hs;          // [128]
    float* cs2_ = (float*)hs + 128;    // [128]
    __syncthreads();
    if (t < 128) { cs_[t] = 0.f; cs2_[t] = 0.f; }
    __syncthreads();
    if (g == 0) {
        #pragma unroll
        for (int nb = 0; nb < 8; nb++) {
            int lc0 = wn*64 + nb*8 + 2*c;
            atomicAdd(&cs_[lc0],      s0[nb]);
            atomicAdd(&cs_[lc0 + 1],  s1[nb]);
            atomicAdd(&cs2_[lc0],     q0[nb]);
            atomicAdd(&cs2_[lc0 + 1], q1[nb]);
        }
    }
    __syncthreads();
    if (t < 128) {
        int gcol = n0 + t;
        atomicAdd(&ps[gcol],      cs_[t]);
        atomicAdd(&ps[Nn + gcol], cs2_[t]);
    }
}

// ---------------- fused attention: vectorized permuted-bias LDG.128 ----------------
// smem halfs: Qh @0 [112][56] (6272), Kh @6272 3x[64][56], Vh @17024 3x[64][56]
// floats from word 13888: uRow[112], consts 6x[48]  -> total 57152 B
__global__ __launch_bounds__(224, 2) void attn_kernel(const __half* __restrict__ Y,
                                                      const __half* __restrict__ Bg,
                                                      const float* __restrict__ ps1,
                                                      const float* __restrict__ g1,
                                                      const float* __restrict__ b1,
                                                      __half* __restrict__ Ohs) {
    extern __shared__ uint32_t sm[];
    float* smf = (float*)sm;
    const int QH = 0, KH = 6272, VH = 17024;
    const int STAGE = 64*56;
    float* uRow = smf + 13888;
    float* aq = smf + 14000; float* bq = smf + 14048;
    float* ak = smf + 14096; float* bk = smf + 14144;
    float* cv = smf + 14192; float* ev = smf + 14240;

    int t = threadIdx.x;
    int w = t >> 5, L = t & 31;
    int g = L >> 2, c = L & 3;
    int m0l = w * 16;
    int bh = blockIdx.y;
    int b = bh >> 3, h = bh & 7;
    int q0 = blockIdx.x * 112;

    uint32_t base = smem_u32(sm);
    uint32_t kBase = base + KH*2, vBase = base + VH*2;

    #define ISSUE_TILE(kt, stage) { \
        int k0i = (kt) * 64; \
        _Pragma("unroll") \
        for (int j = 0; j < 4; j++) { \
            int idx = t + 224*j; \
            if (j < 3 || idx < 768) { \
                int hv  = idx >= 384; \
                int rem = idx - hv*384; \
                int row = rem / 6, seg = rem - row*6; \
                int n = k0i + row; if (n > NN-1) n = NN-1; \
                const __half* src = Y + (size_t)(b*NN + n)*INNER + (hv ? 768 : 384) + h*HD + seg*8; \
                uint32_t dst = (hv ? vBase : kBase) + (stage)*STAGE*2 + (row*56 + seg*8)*2; \
                asm volatile("cp.async.ca.shared.global [%0], [%1], 16;" :: "r"(dst), "l"(src)); \
            } \
        } \
        asm volatile("cp.async.commit_group;"); }

    ISSUE_TILE(0, 0);
    ISSUE_TILE(1, 1);

    // fold constants from BN1 partial sums
    for (int i = t; i < 288; i += 224) {
        int which = i / 48, d = i - which*48;
        int p = which >> 1;
        int ch = p*CC + h*HD + d;
        float mean = ps1[ch] * (1.0f/MM);
        float var  = ps1[INNER + ch] * (1.0f/MM) - mean*mean;
        float sc   = g1[ch] * rsqrtf(var + EPSV);
        float v = (which & 1) ? (b1[ch] - mean*sc) : sc;
        smf[14000 + which*48 + d] = v;
    }
    __syncthreads();

    const float scale = 0.14433756729740643f;
    const float cs = scale * 1.4426950408889634f;

    // Q load + BN fold
    {
        int row = t >> 1, ds = (t & 1) * 24;
        const __half2* src = (const __half2*)(Y + (size_t)(b*NN + q0 + row)*INNER + h*HD + ds);
        float tpart = 0.f;
        #pragma unroll
        for (int j = 0; j < 12; j++) {
            int d = ds + 2*j;
            float2 f = __half22float2(src[j]);
            float q0f = fmaf(f.x, aq[d],   bq[d]);
            float q1f = fmaf(f.y, aq[d+1], bq[d+1]);
            tpart = fmaf(q0f, bk[d], tpart);
            tpart = fmaf(q1f, bk[d+1], tpart);
            sm[QH/2 + row*28 + ds/2 + j] = pack2(q0f*ak[d], q1f*ak[d+1]);
        }
        tpart += __shfl_xor_sync(0xffffffffu, tpart, 1);
        if ((t & 1) == 0) uRow[row] = cs * tpart;
    }
    __syncthreads();

    uint32_t qA = base + QH*2 + ((m0l + (L & 15))*56 + (L >> 4)*8)*2;
    uint32_t qa0[3], qa1[3], qa2[3], qa3[3];
    #pragma unroll
    for (int ks = 0; ks < 3; ks++)
        ldsm4(qa0[ks], qa1[ks], qa2[ks], qa3[ks], qA + ks*32);
    float u0 = uRow[m0l + g];
    float u1 = uRow[m0l + 8 + g];

    int r8 = L & 7, sel = L >> 3;
    uint32_t kB_rel = (uint32_t)((((sel >> 1)*8 + r8)*56 + (sel & 1)*8)*2);
    uint32_t vB_rel = (uint32_t)((((sel & 1)*8 + r8)*56)*2 + (sel >> 1)*16);

    // permuted bias row pointers (uint4 granularity: 8 halfs)
    int qr0 = q0 + m0l + g;
    const uint4* bp0 = (const uint4*)(Bg + ((size_t)h*NN + qr0) * BGW);
    const uint4* bp1 = (const uint4*)(Bg + ((size_t)h*NN + qr0 + 8) * BGW);

    float Oc[6][4] = {};
    float lsum0 = 0.f, lsum1 = 0.f;

    #define DO_TILE(kt, CHECKED) { \
        int k0 = (kt) * 64; \
        uint32_t so = ((kt) % 3) * STAGE*2; \
        if ((kt) < 12) asm volatile("cp.async.wait_group 1;"); \
        else           asm volatile("cp.async.wait_group 0;"); \
        __syncthreads(); \
        if ((kt) + 2 < 13) { ISSUE_TILE((kt) + 2, ((kt) + 2) % 3); } \
        /* bias vector loads (latency hidden behind S-mma) */ \
        uint4 u00 = bp0[(kt)*8 + 2*c], u01 = bp0[(kt)*8 + 2*c + 1]; \
        uint4 u10 = bp1[(kt)*8 + 2*c], u11 = bp1[(kt)*8 + 2*c + 1]; \
        float Sc[8][4] = {}; \
        _Pragma("unroll") \
        for (int ks = 0; ks < 3; ks++) { \
            _Pragma("unroll") \
            for (int nbp = 0; nbp < 4; nbp++) { \
                uint32_t b00, b10, b01, b11; \
                ldsm4(b00, b10, b01, b11, kBase + so + nbp*16*112 + ks*32 + kB_rel); \
                mma_f16(Sc[2*nbp],   qa0[ks], qa1[ks], qa2[ks], qa3[ks], b00, b10); \
                mma_f16(Sc[2*nbp+1], qa0[ks], qa1[ks], qa2[ks], qa3[ks], b01, b11); \
            } \
        } \
        const __half2* w00 = (const __half2*)&u00; \
        const __half2* w01 = (const __half2*)&u01; \
        const __half2* w10 = (const __half2*)&u10; \
        const __half2* w11 = (const __half2*)&u11; \
        float Pv[8][4]; \
        _Pragma("unroll") \
        for (int nb = 0; nb < 8; nb++) { \
            int kj = k0 + nb*8 + 2*c; \
            float p0 = 0.f, p1 = 0.f, p2 = 0.f, p3 = 0.f; \
            float2 fl0 = __half22float2(w00[nb >> 1]); \
            float2 fh0 = __half22float2(w01[nb >> 1]); \
            float2 fl1 = __half22float2(w10[nb >> 1]); \
            float2 fh1 = __half22float2(w11[nb >> 1]); \
            float b0x = (nb & 1) ? fl0.y : fl0.x; \
            float b0y = (nb & 1) ? fh0.y : fh0.x; \
            float b1x = (nb & 1) ? fl1.y : fl1.x; \
            float b1y = (nb & 1) ? fh1.y : fh1.x; \
            if (!CHECKED || kj < NN) { \
                p0 = ex2(fmaf(Sc[nb][0], cs, u0 + b0x)); \
                p2 = ex2(fmaf(Sc[nb][2], cs, u1 + b1x)); \
                if (!CHECKED || kj + 1 < NN) { \
                    p1 = ex2(fmaf(Sc[nb][1], cs, u0 + b0y)); \
                    p3 = ex2(fmaf(Sc[nb][3], cs, u1 + b1y)); \
                } \
            } \
            Pv[nb][0] = p0; Pv[nb][1] = p1; Pv[nb][2] = p2; Pv[nb][3] = p3; \
            lsum0 += p0 + p1; lsum1 += p2 + p3; \
        } \
        _Pragma("unroll") \
        for (int ks = 0; ks < 4; ks++) { \
            uint32_t a0 = pack2(Pv[2*ks][0],   Pv[2*ks][1]); \
            uint32_t a1 = pack2(Pv[2*ks][2],   Pv[2*ks][3]); \
            uint32_t a2 = pack2(Pv[2*ks+1][0], Pv[2*ks+1][1]); \
            uint32_t a3 = pack2(Pv[2*ks+1][2], Pv[2*ks+1][3]); \
            _Pragma("unroll") \
            for (int nbp = 0; nbp < 3; nbp++) { \
                uint32_t b00, b10, b01, b11; \
                ldsm4t(b00, b10, b01, b11, vBase + so + ks*16*112 + nbp*32 + vB_rel); \
                mma_f16(Oc[2*nbp],   a0, a1, a2, a3, b00, b10); \
                mma_f16(Oc[2*nbp+1], a0, a1, a2, a3, b01, b11); \
            } \
        } }

    for (int kt = 0; kt < 12; kt++) DO_TILE(kt, 0);
    DO_TILE(12, 1);
    #undef DO_TILE
    #undef ISSUE_TILE

    lsum0 += __shfl_xor_sync(0xffffffffu, lsum0, 1);
    lsum0 += __shfl_xor_sync(0xffffffffu, lsum0, 2);
    lsum1 += __shfl_xor_sync(0xffffffffu, lsum1, 1);
    lsum1 += __shfl_xor_sync(0xffffffffu, lsum1, 2);

    float inv0 = 1.0f / lsum0;
    float inv1 = 1.0f / lsum1;
    int n0g = q0 + m0l + g, n1g = n0g + 8;
    __half2* O2 = (__half2*)Ohs;
    #pragma unroll
    for (int nb = 0; nb < 6; nb++) {
        int d = nb*8 + 2*c;
        float o00 = fmaf(Oc[nb][0]*inv0, cv[d],   ev[d]);
        float o01 = fmaf(Oc[nb][1]*inv0, cv[d+1], ev[d+1]);
        float o10 = fmaf(Oc[nb][2]*inv1, cv[d],   ev[d]);
        float o11 = fmaf(Oc[nb][3]*inv1, cv[d+1], ev[d+1]);
        O2[((size_t)(b*NN + n0g)*CC + h*HD + d) >> 1] = __floats2half2_rn(hswish(o00), hswish(o01));
        O2[((size_t)(b*NN + n1g)*CC + h*HD + d) >> 1] = __floats2half2_rn(hswish(o10), hswish(o11));
    }
}

// ---------------- final BN apply (stats from ps2) ----------------
__global__ __launch_bounds__(256) void apply_bn(const float* __restrict__ Z,
                                                const float* __restrict__ ps2,
                                                const float* __restrict__ gamma,
                                                const float* __restrict__ beta,
                                                float* __restrict__ out) {
    size_t base = ((size_t)blockIdx.x * 256 + threadIdx.x) * 4;
    if (base < (size_t)MM * CC) {
        float4 z = *(const float4*)(Z + base);
        int c = (int)(base % CC);
        float o[4];
        float zv[4] = {z.x, z.y, z.z, z.w};
        #pragma unroll
        for (int j = 0; j < 4; j++) {
            int cc = c + j;
            float mean = ps2[cc] * (1.0f/MM);
            float var  = ps2[CC + cc] * (1.0f/MM) - mean*mean;
            float sc   = gamma[cc] * rsqrtf(var + EPSV);
            o[j] = zv[j] * sc + (beta[cc] - mean * sc);
        }
        *(float4*)(out + base) = make_float4(o[0], o[1], o[2], o[3]);
    }
}

extern "C" void kernel_launch(void* const* d_in, const int* in_sizes, int n_in,
                              void* d_out, int out_size) {
    const float* x      = (const float*)d_in[0];
    const float* Wqkv   = (const float*)d_in[1];
    const float* g1     = (const float*)d_in[2];
    const float* b1     = (const float*)d_in[3];
    const float* Wproj  = (const float*)d_in[4];
    const float* g2     = (const float*)d_in[5];
    const float* b2     = (const float*)d_in[6];
    const float* biases = (const float*)d_in[7];
    float* out = (float*)d_out;

    __half *xh, *wqh, *wph, *yh, *ohsh, *bg;
    float *zp, *ps1, *ps2;
    cudaGetSymbolAddress((void**)&xh,   g_xh);
    cudaGetSymbolAddress((void**)&wqh,  g_wqh);
    cudaGetSymbolAddress((void**)&wph,  g_wph);
    cudaGetSymbolAddress((void**)&yh,   g_yh);
    cudaGetSymbolAddress((void**)&ohsh, g_ohsh);
    cudaGetSymbolAddress((void**)&zp,   g_z);
    cudaGetSymbolAddress((void**)&bg,   g_bg);
    cudaGetSymbolAddress((void**)&ps1,  g_ps1);
    cudaGetSymbolAddress((void**)&ps2,  g_ps2);

    cudaFuncSetAttribute(gemm_cp<1>, cudaFuncAttributeMaxDynamicSharedMemorySize, 81920);
    cudaFuncSetAttribute(gemm_cp<0>, cudaFuncAttributeMaxDynamicSharedMemorySize, 81920);
    cudaFuncSetAttribute(attn_kernel, cudaFuncAttributeMaxDynamicSharedMemorySize, 57152);

    int nthreads = N4_ALL + 2*INNER + 2*CC;
    f2h_all<<<(nthreads + 255)/256, 256>>>(x, Wqkv, Wproj);
    bias_expand<<<dim3(NN, HH), 256>>>(biases);

    gemm_cp<1><<<dim3(INNER/128, MM/128), 256, 81920>>>(xh, wqh, yh, INNER, ps1);
    attn_kernel<<<dim3(7, BB*HH), 224, 57152>>>(yh, bg, ps1, g1, b1, ohsh);
    gemm_cp<0><<<dim3(CC/128, MM/128), 256, 81920>>>(ohsh, wph, zp, CC, ps2);
    apply_bn<<<(MM*CC/4 + 255)/256, 256>>>(zp, ps2, g2, b2, out);
}